// round 9
// baseline (speedup 1.0000x reference)
#include <cuda_runtime.h>
#include <math.h>

#define B 8
#define CIN 512
#define COUT 128
#define HW16 256   // 16x16
#define HW 196     // 14x14
#define CC 16384   // 128*128

// Scratch (device globals -- no allocation allowed)
__device__ float g_y[B * COUT * HW16];                 // 262144 floats
__device__ float g_A[B * COUT * HW];                   // 200704 floats
__device__ float g_R[(size_t)B * COUT * COUT * HW];    // 25,690,112 floats (~98 MB)
__device__ float g_cij[B * CC];                        // 131072 floats

// ---------------------------------------------------------------------------
// Kernel 1: 1x1 conv (GEMM) + ReLU.  Y[b,o,p] = relu(sum_i W[o,i] * X[b,i,p])
// grid (B, 8 o-tiles of 16), block 256 (thread = spatial position p)
// ---------------------------------------------------------------------------
__global__ void k_gemm_relu(const float* __restrict__ x, const float* __restrict__ w) {
    int b = blockIdx.x;
    int ot = blockIdx.y;
    int p = threadIdx.x;

    __shared__ float Wsm[16][CIN];
    for (int idx = threadIdx.x; idx < 16 * CIN; idx += 256) {
        int r = idx >> 9;
        int i = idx & (CIN - 1);
        Wsm[r][i] = w[(ot * 16 + r) * CIN + i];
    }
    __syncthreads();

    float acc[16];
#pragma unroll
    for (int r = 0; r < 16; ++r) acc[r] = 0.f;

    const float* xb = x + (size_t)b * CIN * HW16 + p;
    for (int i = 0; i < CIN; ++i) {
        float xv = xb[(size_t)i * HW16];
#pragma unroll
        for (int r = 0; r < 16; ++r) acc[r] = fmaf(Wsm[r][i], xv, acc[r]);
    }

    float* yb = g_y + ((size_t)b * COUT + ot * 16) * HW16 + p;
#pragma unroll
    for (int r = 0; r < 16; ++r) yb[(size_t)r * HW16] = fmaxf(acc[r], 0.f);
}

// ---------------------------------------------------------------------------
// Kernel 2: depthwise 3x3 Gaussian, VALID padding.  16x16 -> 14x14.
// ---------------------------------------------------------------------------
__global__ void k_dwconv() {
    int idx = blockIdx.x * 256 + threadIdx.x;
    if (idx >= B * COUT * HW) return;
    int p  = idx % HW;
    int bc = idx / HW;
    int ow = p % 14;
    int oh = p / 14;
    const float* yb = g_y + (size_t)bc * HW16;

    const float W0 = 0.63661977236758134308f;   // 1/(2*pi*0.25)
    const float W1 = W0 * expf(-2.0f);
    const float W2 = W0 * expf(-4.0f);

#define Yv(r, cl) yb[(oh + (r)) * 16 + (ow + (cl))]
    float s = W2 * (Yv(0,0) + Yv(0,2) + Yv(2,0) + Yv(2,2))
            + W1 * (Yv(0,1) + Yv(1,0) + Yv(1,2) + Yv(2,1))
            + W0 *  Yv(1,1);
#undef Yv
    g_A[idx] = s;
}

// ---------------------------------------------------------------------------
// Kernel 3: circular convolution for all channel pairs.
//   R[b,a,c,p] = sum_j A[b,c,j] * A[b,a,(p-j) mod 196]
// grid (a=128, b=8), block 196 threads = 49 p-groups x 4 c-groups.
// Thread: 4 consecutive p, 32 c's (2 at a time).  A tile + duplicated a-row
// live in dynamic shared memory (~102 KB).
// ---------------------------------------------------------------------------
__global__ void __launch_bounds__(196) k_corr() {
    extern __shared__ float sm[];
    float* Asm = sm;                // [128*196]
    float* fa2 = sm + COUT * HW;    // [392] : a-row duplicated (kills the mod)

    int a = blockIdx.x;
    int b = blockIdx.y;
    const float* Ab = g_A + (size_t)b * COUT * HW;

    for (int i = threadIdx.x; i < COUT * HW; i += 196) Asm[i] = Ab[i];
    const float* fa = Ab + a * HW;
    for (int i = threadIdx.x; i < 2 * HW; i += 196) fa2[i] = fa[i >= HW ? i - HW : i];
    __syncthreads();

    int pg = threadIdx.x % 49;
    int cg = threadIdx.x / 49;
    int p0 = pg * 4;

    float* Rb = g_R + ((size_t)(b * COUT + a)) * (COUT * HW);
    const float* fw = fa2 + p0 + HW;   // fw[k - j] = A[a, (p0+k-j) mod 196]

    for (int cc = 0; cc < 32; cc += 2) {
        int c0 = cg * 32 + cc;
        const float* fc0 = Asm + c0 * HW;
        const float* fc1 = fc0 + HW;

        float a00 = 0.f, a01 = 0.f, a02 = 0.f, a03 = 0.f;
        float a10 = 0.f, a11 = 0.f, a12 = 0.f, a13 = 0.f;

#pragma unroll 4
        for (int j = 0; j < HW; ++j) {
            float v0 = fw[0 - j];
            float v1 = fw[1 - j];
            float v2 = fw[2 - j];
            float v3 = fw[3 - j];
            float b0 = fc0[j];
            float b1 = fc1[j];
            a00 = fmaf(v0, b0, a00); a01 = fmaf(v1, b0, a01);
            a02 = fmaf(v2, b0, a02); a03 = fmaf(v3, b0, a03);
            a10 = fmaf(v0, b1, a10); a11 = fmaf(v1, b1, a11);
            a12 = fmaf(v2, b1, a12); a13 = fmaf(v3, b1, a13);
        }

        *reinterpret_cast<float4*>(Rb + c0 * HW + p0)       = make_float4(a00, a01, a02, a03);
        *reinterpret_cast<float4*>(Rb + (c0 + 1) * HW + p0) = make_float4(a10, a11, a12, a13);
    }
}

// ---------------------------------------------------------------------------
// Kernel 4: out[b,v] = sqrt(max_u R_flat[b, u*16384 + v]),  u in [0,196).
// Flat (a,c,p) order of g_R makes this a coalesced strided gather.
// ---------------------------------------------------------------------------
__global__ void k_maxred() {
    int idx = blockIdx.x * 256 + threadIdx.x;   // < 131072
    int b = idx >> 14;
    int v = idx & (CC - 1);
    const float* Rb = g_R + (size_t)b * (COUT * COUT * HW) + v;
    float m = 0.f;   // R >= 0 always (relu + nonneg gaussian)
#pragma unroll 4
    for (int u = 0; u < HW; ++u) m = fmaxf(m, Rb[(size_t)u * CC]);
    g_cij[idx] = sqrtf(m);
}

// ---------------------------------------------------------------------------
// Kernel 5: per-batch normalize: out = c_ij / (sum(c_ij^2) + EPS)
// ---------------------------------------------------------------------------
__global__ void k_norm(float* __restrict__ out) {
    int b = blockIdx.x;
    __shared__ float red[256];
    const float* cb = g_cij + b * CC;

    float s = 0.f;
    for (int v = threadIdx.x; v < CC; v += 256) {
        float c = cb[v];
        s += c * c;
    }
    red[threadIdx.x] = s;
    __syncthreads();
    for (int st = 128; st > 0; st >>= 1) {
        if (threadIdx.x < st) red[threadIdx.x] += red[threadIdx.x + st];
        __syncthreads();
    }
    float inv = 1.0f / (red[0] + 1e-11f);

    float* ob = out + b * CC;
    for (int v = threadIdx.x; v < CC; v += 256) ob[v] = cb[v] * inv;
}

// ---------------------------------------------------------------------------
extern "C" void kernel_launch(void* const* d_in, const int* in_sizes, int n_in,
                              void* d_out, int out_size) {
    const float* x = (const float*)d_in[0];   // (8, 512, 16, 16)
    const float* w = (const float*)d_in[1];   // (128, 512)
    float* out = (float*)d_out;               // (8, 16384)

    const int smem3 = (COUT * HW + 2 * HW) * (int)sizeof(float);  // 101,920 B
    cudaFuncSetAttribute(k_corr, cudaFuncAttributeMaxDynamicSharedMemorySize, smem3);

    k_gemm_relu<<<dim3(B, 8), 256>>>(x, w);
    k_dwconv<<<(B * COUT * HW + 255) / 256, 256>>>();
    k_corr<<<dim3(COUT, B), 196, smem3>>>();
    k_maxred<<<(B * CC) / 256, 256>>>();
    k_norm<<<B, 256>>>(out);
}

// round 12
// speedup vs baseline: 1.4900x; 1.4900x over previous
#include <cuda_runtime.h>
#include <math.h>

#define B 8
#define CIN 512
#define COUT 128
#define HW16 256   // 16x16
#define HW 196     // 14x14
#define CC 16384   // 128*128
#define ASTRIDE 197  // padded row stride for bank-conflict-free b loads

// Scratch (device globals -- no allocation allowed)
__device__ float g_y[B * COUT * HW16];                               // 262144 floats
__device__ float g_A[B * COUT * HW];                                 // 200704 floats
__device__ __align__(16) float g_R[(size_t)B * COUT * COUT * HW];    // ~98 MB
__device__ __align__(16) float g_cij[B * CC];                        // 131072 floats

// ---------------------------------------------------------------------------
// packed f32x2 helpers (sm_103a)
// ---------------------------------------------------------------------------
__device__ __forceinline__ unsigned long long splat2(float b) {
    unsigned long long r;
    asm("mov.b64 %0, {%1, %1};" : "=l"(r) : "f"(b));
    return r;
}
__device__ __forceinline__ void fma2(unsigned long long& acc,
                                     unsigned long long v,
                                     unsigned long long b) {
    asm("fma.rn.f32x2 %0, %1, %2, %0;" : "+l"(acc) : "l"(v), "l"(b));
}

// ---------------------------------------------------------------------------
// Kernel 1: 1x1 conv (GEMM) + ReLU.  Y[b,o,p] = relu(sum_i W[o,i] * X[b,i,p])
// ---------------------------------------------------------------------------
__global__ void k_gemm_relu(const float* __restrict__ x, const float* __restrict__ w) {
    int b = blockIdx.x;
    int ot = blockIdx.y;
    int p = threadIdx.x;

    __shared__ float Wsm[16][CIN];
    for (int idx = threadIdx.x; idx < 16 * CIN; idx += 256) {
        int r = idx >> 9;
        int i = idx & (CIN - 1);
        Wsm[r][i] = w[(ot * 16 + r) * CIN + i];
    }
    __syncthreads();

    float acc[16];
#pragma unroll
    for (int r = 0; r < 16; ++r) acc[r] = 0.f;

    const float* xb = x + (size_t)b * CIN * HW16 + p;
    for (int i = 0; i < CIN; ++i) {
        float xv = xb[(size_t)i * HW16];
#pragma unroll
        for (int r = 0; r < 16; ++r) acc[r] = fmaf(Wsm[r][i], xv, acc[r]);
    }

    float* yb = g_y + ((size_t)b * COUT + ot * 16) * HW16 + p;
#pragma unroll
    for (int r = 0; r < 16; ++r) yb[(size_t)r * HW16] = fmaxf(acc[r], 0.f);
}

// ---------------------------------------------------------------------------
// Kernel 2: depthwise 3x3 Gaussian, VALID padding.  16x16 -> 14x14.
// ---------------------------------------------------------------------------
__global__ void k_dwconv() {
    int idx = blockIdx.x * 256 + threadIdx.x;
    if (idx >= B * COUT * HW) return;
    int p  = idx % HW;
    int bc = idx / HW;
    int ow = p % 14;
    int oh = p / 14;
    const float* yb = g_y + (size_t)bc * HW16;

    const float W0 = 0.63661977236758134308f;   // 1/(2*pi*0.25)
    const float W1 = W0 * expf(-2.0f);
    const float W2 = W0 * expf(-4.0f);

#define Yv(r, cl) yb[(oh + (r)) * 16 + (ow + (cl))]
    float s = W2 * (Yv(0,0) + Yv(0,2) + Yv(2,0) + Yv(2,2))
            + W1 * (Yv(0,1) + Yv(1,0) + Yv(1,2) + Yv(2,1))
            + W0 *  Yv(1,1);
#undef Yv
    g_A[idx] = s;
}

// ---------------------------------------------------------------------------
// Kernel 3: circular convolution over all channel pairs (packed f32x2).
//   R[b,a,c,p] = sum_j A[b,c,j] * A[b,a,(p-j) mod 196]
// grid (a=128, b=8), block 224 = 14 p-groups x 16 c-lanes.
// Thread: p-tile 14 (7 aligned float2 pairs), 8 c's in two passes of 4.
//   - Asm padded to stride 197: 16 consecutive c rows -> 16 distinct banks.
//   - fa2 / fa2b (shifted-by-1 copy) make the sliding-window pair loads
//     8B-aligned LDS.64 for both j parities, broadcast across the 16 c-lanes.
// ---------------------------------------------------------------------------
__global__ void __launch_bounds__(224, 2) k_corr() {
    extern __shared__ float sm[];
    float* Asm  = sm;                    // [128 * 197]
    float* fa2  = sm + COUT * ASTRIDE;   // [392]
    float* fa2b = fa2 + 392;             // [392]  fa2b[i] = fa2[i+1]

    int a = blockIdx.x;
    int b = blockIdx.y;
    const float* Ab = g_A + (size_t)b * COUT * HW;

    for (int i = threadIdx.x; i < COUT * HW; i += 224) {
        int r = i / HW;
        int q = i - r * HW;
        Asm[r * ASTRIDE + q] = Ab[i];
    }
    const float* fa = Ab + a * HW;
    for (int i = threadIdx.x; i < 392; i += 224) {
        fa2[i]  = fa[(i >= HW) ? i - HW : i];
        fa2b[i] = fa[(i + 1) % HW];
    }
    __syncthreads();

    int cg = threadIdx.x & 15;       // c lane within warp
    int pg = threadIdx.x >> 4;       // 0..13
    int p0 = pg * 14;                // even

    float* Rb = g_R + ((size_t)(b * COUT + a)) * (COUT * HW);

#pragma unroll
    for (int ci = 0; ci < 8; ci += 4) {
        const float* f0 = Asm + (cg + 16 * (ci + 0)) * ASTRIDE;
        const float* f1 = Asm + (cg + 16 * (ci + 1)) * ASTRIDE;
        const float* f2 = Asm + (cg + 16 * (ci + 2)) * ASTRIDE;
        const float* f3 = Asm + (cg + 16 * (ci + 3)) * ASTRIDE;

        unsigned long long acc[4][7];
#pragma unroll
        for (int k = 0; k < 4; ++k)
#pragma unroll
            for (int t = 0; t < 7; ++t) acc[k][t] = 0ull;  // (0.f, 0.f)

#pragma unroll 2
        for (int j = 0; j < HW; j += 2) {
            // ---- even j: pairs aligned in fa2 ----
            {
                const float* base = fa2 + (p0 + HW - j);          // even word
                unsigned long long B0 = splat2(f0[j]);
                unsigned long long B1 = splat2(f1[j]);
                unsigned long long B2 = splat2(f2[j]);
                unsigned long long B3 = splat2(f3[j]);
#pragma unroll
                for (int t = 0; t < 7; ++t) {
                    unsigned long long v =
                        *reinterpret_cast<const unsigned long long*>(base + 2 * t);
                    fma2(acc[0][t], v, B0);
                    fma2(acc[1][t], v, B1);
                    fma2(acc[2][t], v, B2);
                    fma2(acc[3][t], v, B3);
                }
            }
            // ---- odd j+1: pairs aligned in shifted copy fa2b ----
            {
                const float* base = fa2b + (p0 + HW - j - 2);     // even word
                unsigned long long B0 = splat2(f0[j + 1]);
                unsigned long long B1 = splat2(f1[j + 1]);
                unsigned long long B2 = splat2(f2[j + 1]);
                unsigned long long B3 = splat2(f3[j + 1]);
#pragma unroll
                for (int t = 0; t < 7; ++t) {
                    unsigned long long v =
                        *reinterpret_cast<const unsigned long long*>(base + 2 * t);
                    fma2(acc[0][t], v, B0);
                    fma2(acc[1][t], v, B1);
                    fma2(acc[2][t], v, B2);
                    fma2(acc[3][t], v, B3);
                }
            }
        }

#pragma unroll
        for (int k = 0; k < 4; ++k) {
            float* dst = Rb + (size_t)(cg + 16 * (ci + k)) * HW + p0;  // 8B aligned
#pragma unroll
            for (int t = 0; t < 7; ++t)
                *reinterpret_cast<unsigned long long*>(dst + 2 * t) = acc[k][t];
        }
    }
}

// ---------------------------------------------------------------------------
// Kernel 4: out[b,v] = sqrt(max_u R_flat[b, u*16384 + v]),  u in [0,196).
// float4-vectorized coalesced strided gather; unroll for MLP.
// ---------------------------------------------------------------------------
__global__ void k_maxred() {
    int idx = blockIdx.x * 128 + threadIdx.x;   // 32768 float4 slots
    int b = idx >> 12;                          // 4096 float4 per batch
    int v4 = idx & 4095;
    const float4* Rb =
        reinterpret_cast<const float4*>(g_R + (size_t)b * (COUT * COUT * HW)) + v4;
    float4 m = make_float4(0.f, 0.f, 0.f, 0.f);
#pragma unroll 14
    for (int u = 0; u < HW; ++u) {
        float4 r = Rb[(size_t)u * (CC / 4)];
        m.x = fmaxf(m.x, r.x);
        m.y = fmaxf(m.y, r.y);
        m.z = fmaxf(m.z, r.z);
        m.w = fmaxf(m.w, r.w);
    }
    float4 o;
    o.x = sqrtf(m.x);
    o.y = sqrtf(m.y);
    o.z = sqrtf(m.z);
    o.w = sqrtf(m.w);
    reinterpret_cast<float4*>(g_cij)[idx] = o;
}

// ---------------------------------------------------------------------------
// Kernel 5: per-batch normalize: out = c_ij / (sum(c_ij^2) + EPS)
// ---------------------------------------------------------------------------
__global__ void k_norm(float* __restrict__ out) {
    int b = blockIdx.x;
    __shared__ float red[256];
    const float* cb = g_cij + b * CC;

    float s = 0.f;
    for (int v = threadIdx.x; v < CC; v += 256) {
        float c = cb[v];
        s += c * c;
    }
    red[threadIdx.x] = s;
    __syncthreads();
    for (int st = 128; st > 0; st >>= 1) {
        if (threadIdx.x < st) red[threadIdx.x] += red[threadIdx.x + st];
        __syncthreads();
    }
    float inv = 1.0f / (red[0] + 1e-11f);

    float* ob = out + b * CC;
    for (int v = threadIdx.x; v < CC; v += 256) ob[v] = cb[v] * inv;
}

// ---------------------------------------------------------------------------
extern "C" void kernel_launch(void* const* d_in, const int* in_sizes, int n_in,
                              void* d_out, int out_size) {
    const float* x = (const float*)d_in[0];   // (8, 512, 16, 16)
    const float* w = (const float*)d_in[1];   // (128, 512)
    float* out = (float*)d_out;               // (8, 16384)

    const int smem3 = (COUT * ASTRIDE + 2 * 392) * (int)sizeof(float);  // 104,000 B
    cudaFuncSetAttribute(k_corr, cudaFuncAttributeMaxDynamicSharedMemorySize, smem3);

    k_gemm_relu<<<dim3(B, 8), 256>>>(x, w);
    k_dwconv<<<(B * COUT * HW + 255) / 256, 256>>>();
    k_corr<<<dim3(COUT, B), 224, smem3>>>();
    k_maxred<<<(B * CC / 4) / 128, 128>>>();
    k_norm<<<B, 256>>>(out);
}

// round 13
// speedup vs baseline: 1.4926x; 1.0017x over previous
#include <cuda_runtime.h>
#include <math.h>

#define B 8
#define CIN 512
#define COUT 128
#define HW16 256   // 16x16
#define HW 196     // 14x14
#define CC 16384   // 128*128
#define ASTRIDE 197  // padded row stride for bank-conflict-free b loads

// Scratch (device globals -- no allocation allowed)
__device__ float g_y[B * COUT * HW16];                               // 262144 floats
__device__ float g_A[B * COUT * HW];                                 // 200704 floats
__device__ __align__(16) float g_R[(size_t)B * COUT * COUT * HW];    // ~98 MB
__device__ __align__(16) float g_cij[B * CC];                        // 131072 floats

// ---------------------------------------------------------------------------
// packed f32x2 helpers (sm_103a)
// ---------------------------------------------------------------------------
__device__ __forceinline__ unsigned long long splat2(float b) {
    unsigned long long r;
    asm("mov.b64 %0, {%1, %1};" : "=l"(r) : "f"(b));
    return r;
}
__device__ __forceinline__ void fma2(unsigned long long& acc,
                                     unsigned long long v,
                                     unsigned long long b) {
    asm("fma.rn.f32x2 %0, %1, %2, %0;" : "+l"(acc) : "l"(v), "l"(b));
}

// ---------------------------------------------------------------------------
// Kernel 1: 1x1 conv (GEMM) + ReLU.  Y[b,o,p] = relu(sum_i W[o,i] * X[b,i,p])
// ---------------------------------------------------------------------------
__global__ void k_gemm_relu(const float* __restrict__ x, const float* __restrict__ w) {
    int b = blockIdx.x;
    int ot = blockIdx.y;
    int p = threadIdx.x;

    __shared__ float Wsm[16][CIN];
    for (int idx = threadIdx.x; idx < 16 * CIN; idx += 256) {
        int r = idx >> 9;
        int i = idx & (CIN - 1);
        Wsm[r][i] = w[(ot * 16 + r) * CIN + i];
    }
    __syncthreads();

    float acc[16];
#pragma unroll
    for (int r = 0; r < 16; ++r) acc[r] = 0.f;

    const float* xb = x + (size_t)b * CIN * HW16 + p;
    for (int i = 0; i < CIN; ++i) {
        float xv = xb[(size_t)i * HW16];
#pragma unroll
        for (int r = 0; r < 16; ++r) acc[r] = fmaf(Wsm[r][i], xv, acc[r]);
    }

    float* yb = g_y + ((size_t)b * COUT + ot * 16) * HW16 + p;
#pragma unroll
    for (int r = 0; r < 16; ++r) yb[(size_t)r * HW16] = fmaxf(acc[r], 0.f);
}

// ---------------------------------------------------------------------------
// Kernel 2: depthwise 3x3 Gaussian, VALID padding.  16x16 -> 14x14.
// ---------------------------------------------------------------------------
__global__ void k_dwconv() {
    int idx = blockIdx.x * 256 + threadIdx.x;
    if (idx >= B * COUT * HW) return;
    int p  = idx % HW;
    int bc = idx / HW;
    int ow = p % 14;
    int oh = p / 14;
    const float* yb = g_y + (size_t)bc * HW16;

    const float W0 = 0.63661977236758134308f;   // 1/(2*pi*0.25)
    const float W1 = W0 * expf(-2.0f);
    const float W2 = W0 * expf(-4.0f);

#define Yv(r, cl) yb[(oh + (r)) * 16 + (ow + (cl))]
    float s = W2 * (Yv(0,0) + Yv(0,2) + Yv(2,0) + Yv(2,2))
            + W1 * (Yv(0,1) + Yv(1,0) + Yv(1,2) + Yv(2,1))
            + W0 *  Yv(1,1);
#undef Yv
    g_A[idx] = s;
}

// ---------------------------------------------------------------------------
// Kernel 3: circular convolution over all channel pairs (packed f32x2).
//   R[b,a,c,p] = sum_j A[b,c,j] * A[b,a,(p-j) mod 196]
// grid (a=128, b=8), block 224 = 14 p-groups x 16 c-lanes.
// Thread: p-tile 14 (7 aligned float2 pairs), 8 c's in two passes of 4.
//   - Asm padded to stride 197: 16 consecutive c rows -> 16 distinct banks.
//   - fa2 / fa2b (shifted-by-1 copy) make the sliding-window pair loads
//     8B-aligned LDS.64 for both j parities, broadcast across the 16 c-lanes.
// ---------------------------------------------------------------------------
__global__ void __launch_bounds__(224, 2) k_corr() {
    extern __shared__ float sm[];
    float* Asm  = sm;                    // [128 * 197]
    float* fa2  = sm + COUT * ASTRIDE;   // [392]
    float* fa2b = fa2 + 392;             // [392]  fa2b[i] = fa2[i+1]

    int a = blockIdx.x;
    int b = blockIdx.y;
    const float* Ab = g_A + (size_t)b * COUT * HW;

    for (int i = threadIdx.x; i < COUT * HW; i += 224) {
        int r = i / HW;
        int q = i - r * HW;
        Asm[r * ASTRIDE + q] = Ab[i];
    }
    const float* fa = Ab + a * HW;
    for (int i = threadIdx.x; i < 392; i += 224) {
        fa2[i]  = fa[(i >= HW) ? i - HW : i];
        fa2b[i] = fa[(i + 1) % HW];
    }
    __syncthreads();

    int cg = threadIdx.x & 15;       // c lane within warp
    int pg = threadIdx.x >> 4;       // 0..13
    int p0 = pg * 14;                // even

    float* Rb = g_R + ((size_t)(b * COUT + a)) * (COUT * HW);

#pragma unroll
    for (int ci = 0; ci < 8; ci += 4) {
        const float* f0 = Asm + (cg + 16 * (ci + 0)) * ASTRIDE;
        const float* f1 = Asm + (cg + 16 * (ci + 1)) * ASTRIDE;
        const float* f2 = Asm + (cg + 16 * (ci + 2)) * ASTRIDE;
        const float* f3 = Asm + (cg + 16 * (ci + 3)) * ASTRIDE;

        unsigned long long acc[4][7];
#pragma unroll
        for (int k = 0; k < 4; ++k)
#pragma unroll
            for (int t = 0; t < 7; ++t) acc[k][t] = 0ull;  // (0.f, 0.f)

#pragma unroll 2
        for (int j = 0; j < HW; j += 2) {
            // ---- even j: pairs aligned in fa2 ----
            {
                const float* base = fa2 + (p0 + HW - j);          // even word
                unsigned long long B0 = splat2(f0[j]);
                unsigned long long B1 = splat2(f1[j]);
                unsigned long long B2 = splat2(f2[j]);
                unsigned long long B3 = splat2(f3[j]);
#pragma unroll
                for (int t = 0; t < 7; ++t) {
                    unsigned long long v =
                        *reinterpret_cast<const unsigned long long*>(base + 2 * t);
                    fma2(acc[0][t], v, B0);
                    fma2(acc[1][t], v, B1);
                    fma2(acc[2][t], v, B2);
                    fma2(acc[3][t], v, B3);
                }
            }
            // ---- odd j+1: pairs aligned in shifted copy fa2b ----
            {
                const float* base = fa2b + (p0 + HW - j - 2);     // even word
                unsigned long long B0 = splat2(f0[j + 1]);
                unsigned long long B1 = splat2(f1[j + 1]);
                unsigned long long B2 = splat2(f2[j + 1]);
                unsigned long long B3 = splat2(f3[j + 1]);
#pragma unroll
                for (int t = 0; t < 7; ++t) {
                    unsigned long long v =
                        *reinterpret_cast<const unsigned long long*>(base + 2 * t);
                    fma2(acc[0][t], v, B0);
                    fma2(acc[1][t], v, B1);
                    fma2(acc[2][t], v, B2);
                    fma2(acc[3][t], v, B3);
                }
            }
        }

#pragma unroll
        for (int k = 0; k < 4; ++k) {
            float* dst = Rb + (size_t)(cg + 16 * (ci + k)) * HW + p0;  // 8B aligned
#pragma unroll
            for (int t = 0; t < 7; ++t)
                *reinterpret_cast<unsigned long long*>(dst + 2 * t) = acc[k][t];
        }
    }
}

// ---------------------------------------------------------------------------
// Kernel 4: out[b,v] = sqrt(max_u R_flat[b, u*16384 + v]),  u in [0,196).
// float4-vectorized coalesced strided gather; unroll for MLP.
// ---------------------------------------------------------------------------
__global__ void k_maxred() {
    int idx = blockIdx.x * 128 + threadIdx.x;   // 32768 float4 slots
    int b = idx >> 12;                          // 4096 float4 per batch
    int v4 = idx & 4095;
    const float4* Rb =
        reinterpret_cast<const float4*>(g_R + (size_t)b * (COUT * COUT * HW)) + v4;
    float4 m = make_float4(0.f, 0.f, 0.f, 0.f);
#pragma unroll 14
    for (int u = 0; u < HW; ++u) {
        float4 r = Rb[(size_t)u * (CC / 4)];
        m.x = fmaxf(m.x, r.x);
        m.y = fmaxf(m.y, r.y);
        m.z = fmaxf(m.z, r.z);
        m.w = fmaxf(m.w, r.w);
    }
    float4 o;
    o.x = sqrtf(m.x);
    o.y = sqrtf(m.y);
    o.z = sqrtf(m.z);
    o.w = sqrtf(m.w);
    reinterpret_cast<float4*>(g_cij)[idx] = o;
}

// ---------------------------------------------------------------------------
// Kernel 5: per-batch normalize: out = c_ij / (sum(c_ij^2) + EPS)
// ---------------------------------------------------------------------------
__global__ void k_norm(float* __restrict__ out) {
    int b = blockIdx.x;
    __shared__ float red[256];
    const float* cb = g_cij + b * CC;

    float s = 0.f;
    for (int v = threadIdx.x; v < CC; v += 256) {
        float c = cb[v];
        s += c * c;
    }
    red[threadIdx.x] = s;
    __syncthreads();
    for (int st = 128; st > 0; st >>= 1) {
        if (threadIdx.x < st) red[threadIdx.x] += red[threadIdx.x + st];
        __syncthreads();
    }
    float inv = 1.0f / (red[0] + 1e-11f);

    float* ob = out + b * CC;
    for (int v = threadIdx.x; v < CC; v += 256) ob[v] = cb[v] * inv;
}

// ---------------------------------------------------------------------------
extern "C" void kernel_launch(void* const* d_in, const int* in_sizes, int n_in,
                              void* d_out, int out_size) {
    const float* x = (const float*)d_in[0];   // (8, 512, 16, 16)
    const float* w = (const float*)d_in[1];   // (128, 512)
    float* out = (float*)d_out;               // (8, 16384)

    const int smem3 = (COUT * ASTRIDE + 2 * 392) * (int)sizeof(float);  // 104,000 B
    cudaFuncSetAttribute(k_corr, cudaFuncAttributeMaxDynamicSharedMemorySize, smem3);

    k_gemm_relu<<<dim3(B, 8), 256>>>(x, w);
    k_dwconv<<<(B * COUT * HW + 255) / 256, 256>>>();
    k_corr<<<dim3(COUT, B), 224, smem3>>>();
    k_maxred<<<(B * CC / 4) / 128, 128>>>();
    k_norm<<<B, 256>>>(out);
}